// round 1
// baseline (speedup 1.0000x reference)
#include <cuda_runtime.h>

#define BATCH 4
#define NPTS  16384
#define ROWS  (BATCH*NPTS)     // 65536
#define CIMG  64
#define KIMG  1024
#define D1    128
#define D2    64
#define BN_EPS 1e-5f

// ---------------- scratch (no allocations allowed) ----------------
__device__ __align__(16) float g_y1[(size_t)ROWS*D1];   // 33.5 MB
__device__ __align__(16) float g_y2[(size_t)ROWS*D2];   // 16.8 MB
__device__ float g_gpool[BATCH*CIMG];
__device__ __align__(16) float g_h[BATCH*D1];
__device__ __align__(16) float g_M[BATCH*D2*CIMG];
__device__ __align__(16) float g_dvec[BATCH*CIMG];
__device__ __align__(16) float g_W1t[64*D1];            // [k<64][o<128]  (lidar half of W1)
__device__ __align__(16) float g_W2t[D1*D2];            // [k<128][j<64]
__device__ float g_sum1[D1], g_ss1[D1], g_sum2[D2], g_ss2[D2];
__device__ float g_scale1[D1], g_shift1[D1], g_scale2[D2], g_shift2[D2];

// ---------------- prep: weight transposes + zero stats ----------------
__global__ void k_prep(const float* __restrict__ W1, const float* __restrict__ W2) {
    int i = blockIdx.x * blockDim.x + threadIdx.x;   // 64*256 = 16384 threads
    if (i < 64*D1) {
        int k = i / D1, o = i % D1;
        g_W1t[k*D1 + o] = W1[o*128 + 64 + k];        // lidar channels only
    } else {
        int j2 = i - 64*D1;
        int k = j2 / D2, j = j2 % D2;
        g_W2t[k*D2 + j] = W2[j*D1 + k];
    }
    if (i < D1) { g_sum1[i] = 0.f; g_ss1[i] = 0.f; }
    if (i < D2) { g_sum2[i] = 0.f; g_ss2[i] = 0.f; }
}

// ---------------- pool g, d = img·b3/K, M[b] = (img[b]·W3)/K ----------------
// grid 64 = (b, cgroup of 4), 256 threads
__global__ void k_pool_M(const float* __restrict__ img, const float* __restrict__ W3,
                         const float* __restrict__ b3) {
    __shared__ float srow[4][KIMG];
    __shared__ float red[256], red2[256];
    int b  = blockIdx.x >> 4;
    int cg = blockIdx.x & 15;
    int t  = threadIdx.x;
    int ci = t >> 6, lane = t & 63;
    int c  = cg*4 + ci;
    const float* row = img + (size_t)(b*CIMG + c)*KIMG;

    float s = 0.f, sd = 0.f;
    for (int k = lane; k < KIMG; k += 64) {
        float v = row[k];
        srow[ci][k] = v;
        s += v; sd += v * b3[k];
    }
    red[t] = s; red2[t] = sd;
    __syncthreads();
    for (int off = 32; off >= 1; off >>= 1) {
        if (lane < off) { red[t] += red[t+off]; red2[t] += red2[t+off]; }
        __syncthreads();
    }
    if (lane == 0) {
        g_gpool[b*CIMG + c] = red[t]  * (1.f/KIMG);
        g_dvec [b*CIMG + c] = red2[t] * (1.f/KIMG);
    }
    // thread (ci, j=lane): M[b,j,c] = sum_k srow[ci][k] * W3[k*64+j] / K
    int j = lane;
    float acc = 0.f;
    #pragma unroll 8
    for (int k = 0; k < KIMG; ++k) acc += srow[ci][k] * W3[k*D2 + j];
    g_M[b*(D2*CIMG) + j*CIMG + c] = acc * (1.f/KIMG);
}

// ---------------- h[b,o] = g[b]·W1[o,:64] + b1[o] ----------------
__global__ void k_h(const float* __restrict__ W1, const float* __restrict__ b1) {
    int t = threadIdx.x;          // 512
    int b = t >> 7, o = t & 127;
    float acc = b1[o];
    #pragma unroll 8
    for (int c = 0; c < 64; ++c) acc += g_gpool[b*CIMG + c] * W1[o*128 + c];
    g_h[b*D1 + o] = acc;
}

// ---------------- GEMM1: y1 = lidar·W1tᵀ + h   [65536x128, K=64] ----------------
__global__ __launch_bounds__(256) void k_gemm1(const float* __restrict__ lidar) {
    __shared__ __align__(16) float As[64*64];
    __shared__ __align__(16) float Bs[64*D1];
    int t  = threadIdx.x;
    int tx = t & 15, ty = t >> 4;
    size_t r0 = (size_t)blockIdx.x * 64;

    {
        const float4* src = (const float4*)(lidar + r0*64);
        float4* dst = (float4*)As;
        #pragma unroll
        for (int i = 0; i < 4; ++i) dst[t + 256*i] = src[t + 256*i];
    }
    {
        const float4* src = (const float4*)g_W1t;
        float4* dst = (float4*)Bs;
        #pragma unroll
        for (int i = 0; i < 8; ++i) dst[t + 256*i] = src[t + 256*i];
    }
    __syncthreads();

    float acc[4][8];
    #pragma unroll
    for (int i = 0; i < 4; ++i)
        #pragma unroll
        for (int j = 0; j < 8; ++j) acc[i][j] = 0.f;

    #pragma unroll 8
    for (int k = 0; k < 64; ++k) {
        float a[4];
        #pragma unroll
        for (int i = 0; i < 4; ++i) a[i] = As[(ty*4+i)*64 + k];
        float4 b0 = *(const float4*)&Bs[k*D1 + tx*8];
        float4 b1 = *(const float4*)&Bs[k*D1 + tx*8 + 4];
        #pragma unroll
        for (int i = 0; i < 4; ++i) {
            acc[i][0] = fmaf(a[i], b0.x, acc[i][0]);
            acc[i][1] = fmaf(a[i], b0.y, acc[i][1]);
            acc[i][2] = fmaf(a[i], b0.z, acc[i][2]);
            acc[i][3] = fmaf(a[i], b0.w, acc[i][3]);
            acc[i][4] = fmaf(a[i], b1.x, acc[i][4]);
            acc[i][5] = fmaf(a[i], b1.y, acc[i][5]);
            acc[i][6] = fmaf(a[i], b1.z, acc[i][6]);
            acc[i][7] = fmaf(a[i], b1.w, acc[i][7]);
        }
    }

    int bidx = (int)(blockIdx.x >> 8);   // 256 blocks per batch
    float4 h0 = *(const float4*)&g_h[bidx*D1 + tx*8];
    float4 h1 = *(const float4*)&g_h[bidx*D1 + tx*8 + 4];
    #pragma unroll
    for (int i = 0; i < 4; ++i) {
        float4 o0 = make_float4(acc[i][0]+h0.x, acc[i][1]+h0.y, acc[i][2]+h0.z, acc[i][3]+h0.w);
        float4 o1 = make_float4(acc[i][4]+h1.x, acc[i][5]+h1.y, acc[i][6]+h1.z, acc[i][7]+h1.w);
        float* dst = &g_y1[(r0 + ty*4 + i)*D1 + tx*8];
        *(float4*)dst = o0;
        *(float4*)(dst + 4) = o1;
    }
}

// ---------------- stats over y1 (per-channel sum, sumsq) ----------------
__global__ void k_stats1() {
    __shared__ float rs[256], rss[256];
    int t = threadIdx.x;
    int ch = t & 127, half = t >> 7;
    size_t r0 = (size_t)blockIdx.x * 256;
    float s = 0.f, ss = 0.f;
    #pragma unroll 4
    for (int rr = half; rr < 256; rr += 2) {
        float v = g_y1[(r0+rr)*D1 + ch];
        s += v; ss += v*v;
    }
    rs[t] = s; rss[t] = ss;
    __syncthreads();
    if (t < 128) {
        atomicAdd(&g_sum1[t], rs[t] + rs[t+128]);
        atomicAdd(&g_ss1[t],  rss[t] + rss[t+128]);
    }
}

__global__ void k_fin1(const float* __restrict__ g1, const float* __restrict__ be1) {
    int t = threadIdx.x;   // 128
    const float inv = 1.f / (float)ROWS;
    float mu  = g_sum1[t] * inv;
    float var = fmaxf(g_ss1[t] * inv - mu*mu, 0.f);
    float scale = g1[t] * rsqrtf(var + BN_EPS);
    g_scale1[t] = scale;
    g_shift1[t] = be1[t] - mu*scale;
}

// ---------------- GEMM2: y2 = relu(bn1(y1))·W2tᵀ + b2  [65536x64, K=128] ----------------
__global__ __launch_bounds__(256) void k_gemm2(const float* __restrict__ b2) {
    __shared__ __align__(16) float As[64*64];
    __shared__ __align__(16) float Bs[64*D2];
    __shared__ float sc[D1], sh[D1];
    int t  = threadIdx.x;
    int tx = t & 15, ty = t >> 4;
    size_t r0 = (size_t)blockIdx.x * 64;
    if (t < D1) { sc[t] = g_scale1[t]; sh[t] = g_shift1[t]; }

    float acc[4][4];
    #pragma unroll
    for (int i = 0; i < 4; ++i)
        #pragma unroll
        for (int j = 0; j < 4; ++j) acc[i][j] = 0.f;

    const float4* ybase = (const float4*)(g_y1 + r0*D1);
    for (int kh = 0; kh < 2; ++kh) {
        __syncthreads();
        #pragma unroll
        for (int ii = 0; ii < 4; ++ii) {
            int i = t + 256*ii;          // 0..1023
            int r = i >> 4, kk4 = i & 15;
            float4 v = ybase[r*32 + kh*16 + kk4];
            int k0 = kh*64 + kk4*4;
            v.x = fmaxf(fmaf(v.x, sc[k0  ], sh[k0  ]), 0.f);
            v.y = fmaxf(fmaf(v.y, sc[k0+1], sh[k0+1]), 0.f);
            v.z = fmaxf(fmaf(v.z, sc[k0+2], sh[k0+2]), 0.f);
            v.w = fmaxf(fmaf(v.w, sc[k0+3], sh[k0+3]), 0.f);
            ((float4*)As)[i] = v;
        }
        {
            const float4* src = (const float4*)(g_W2t + kh*64*D2);
            #pragma unroll
            for (int i = 0; i < 4; ++i) ((float4*)Bs)[t + 256*i] = src[t + 256*i];
        }
        __syncthreads();
        #pragma unroll 8
        for (int k = 0; k < 64; ++k) {
            float a[4];
            #pragma unroll
            for (int i = 0; i < 4; ++i) a[i] = As[(ty*4+i)*64 + k];
            float4 bv = *(const float4*)&Bs[k*D2 + tx*4];
            #pragma unroll
            for (int i = 0; i < 4; ++i) {
                acc[i][0] = fmaf(a[i], bv.x, acc[i][0]);
                acc[i][1] = fmaf(a[i], bv.y, acc[i][1]);
                acc[i][2] = fmaf(a[i], bv.z, acc[i][2]);
                acc[i][3] = fmaf(a[i], bv.w, acc[i][3]);
            }
        }
    }
    float4 bb = ((const float4*)b2)[tx];
    #pragma unroll
    for (int i = 0; i < 4; ++i) {
        float4 o0 = make_float4(acc[i][0]+bb.x, acc[i][1]+bb.y, acc[i][2]+bb.z, acc[i][3]+bb.w);
        *(float4*)&g_y2[(r0 + ty*4 + i)*D2 + tx*4] = o0;
    }
}

// ---------------- stats over y2 ----------------
__global__ void k_stats2() {
    __shared__ float rs[256], rss[256];
    int t = threadIdx.x;
    int ch = t & 63, q = t >> 6;
    size_t r0 = (size_t)blockIdx.x * 256;
    float s = 0.f, ss = 0.f;
    #pragma unroll 4
    for (int rr = q; rr < 256; rr += 4) {
        float v = g_y2[(r0+rr)*D2 + ch];
        s += v; ss += v*v;
    }
    rs[t] = s; rss[t] = ss;
    __syncthreads();
    if (t < 64) {
        atomicAdd(&g_sum2[t], rs[t] + rs[t+64] + rs[t+128] + rs[t+192]);
        atomicAdd(&g_ss2[t],  rss[t] + rss[t+64] + rss[t+128] + rss[t+192]);
    }
}

__global__ void k_fin2(const float* __restrict__ g2, const float* __restrict__ be2) {
    int t = threadIdx.x;   // 64
    const float inv = 1.f / (float)ROWS;
    float mu  = g_sum2[t] * inv;
    float var = fmaxf(g_ss2[t] * inv - mu*mu, 0.f);
    float scale = g2[t] * rsqrtf(var + BN_EPS);
    g_scale2[t] = scale;
    g_shift2[t] = be2[t] - mu*scale;
}

// ---------------- GEMM3: out = relu(bn2(y2))·M[b] + d[b]  [65536x64, K=64] ----------------
__global__ __launch_bounds__(256) void k_gemm3(float* __restrict__ out) {
    __shared__ __align__(16) float As[64*64];
    __shared__ __align__(16) float Bs[64*64];
    __shared__ float sc[D2], sh[D2];
    int t  = threadIdx.x;
    int tx = t & 15, ty = t >> 4;
    size_t r0 = (size_t)blockIdx.x * 64;
    int bidx = (int)(blockIdx.x >> 8);
    if (t < D2) { sc[t] = g_scale2[t]; sh[t] = g_shift2[t]; }
    __syncthreads();

    {
        const float4* ybase = (const float4*)(g_y2 + r0*D2);
        #pragma unroll
        for (int ii = 0; ii < 4; ++ii) {
            int i = t + 256*ii;
            int kk4 = i & 15;
            float4 v = ybase[i];
            int k0 = kk4*4;
            v.x = fmaxf(fmaf(v.x, sc[k0  ], sh[k0  ]), 0.f);
            v.y = fmaxf(fmaf(v.y, sc[k0+1], sh[k0+1]), 0.f);
            v.z = fmaxf(fmaf(v.z, sc[k0+2], sh[k0+2]), 0.f);
            v.w = fmaxf(fmaf(v.w, sc[k0+3], sh[k0+3]), 0.f);
            ((float4*)As)[i] = v;
        }
    }
    {
        const float4* src = (const float4*)(g_M + bidx*(D2*CIMG));
        #pragma unroll
        for (int i = 0; i < 4; ++i) ((float4*)Bs)[t + 256*i] = src[t + 256*i];
    }
    __syncthreads();

    float acc[4][4];
    #pragma unroll
    for (int i = 0; i < 4; ++i)
        #pragma unroll
        for (int j = 0; j < 4; ++j) acc[i][j] = 0.f;

    #pragma unroll 8
    for (int k = 0; k < 64; ++k) {
        float a[4];
        #pragma unroll
        for (int i = 0; i < 4; ++i) a[i] = As[(ty*4+i)*64 + k];
        float4 bv = *(const float4*)&Bs[k*64 + tx*4];
        #pragma unroll
        for (int i = 0; i < 4; ++i) {
            acc[i][0] = fmaf(a[i], bv.x, acc[i][0]);
            acc[i][1] = fmaf(a[i], bv.y, acc[i][1]);
            acc[i][2] = fmaf(a[i], bv.z, acc[i][2]);
            acc[i][3] = fmaf(a[i], bv.w, acc[i][3]);
        }
    }

    float4 dv = ((const float4*)(g_dvec + bidx*CIMG))[tx];
    #pragma unroll
    for (int i = 0; i < 4; ++i) {
        float4 o0 = make_float4(acc[i][0]+dv.x, acc[i][1]+dv.y, acc[i][2]+dv.z, acc[i][3]+dv.w);
        *(float4*)&out[(r0 + ty*4 + i)*64 + tx*4] = o0;
    }
}

// ---------------- launch ----------------
extern "C" void kernel_launch(void* const* d_in, const int* in_sizes, int n_in,
                              void* d_out, int out_size) {
    (void)in_sizes; (void)n_in; (void)out_size;
    const float* lidar = (const float*)d_in[0];
    const float* img   = (const float*)d_in[1];
    const float* W1  = (const float*)d_in[2];
    const float* b1  = (const float*)d_in[3];
    const float* g1  = (const float*)d_in[4];
    const float* be1 = (const float*)d_in[5];
    const float* W2  = (const float*)d_in[6];
    const float* b2  = (const float*)d_in[7];
    const float* g2  = (const float*)d_in[8];
    const float* be2 = (const float*)d_in[9];
    const float* W3  = (const float*)d_in[10];
    const float* b3  = (const float*)d_in[11];
    float* out = (float*)d_out;

    k_prep  <<<64, 256>>>(W1, W2);
    k_pool_M<<<64, 256>>>(img, W3, b3);
    k_h     <<<1, 512>>>(W1, b1);
    k_gemm1 <<<ROWS/64, 256>>>(lidar);
    k_stats1<<<ROWS/256, 256>>>();
    k_fin1  <<<1, D1>>>(g1, be1);
    k_gemm2 <<<ROWS/64, 256>>>(b2);
    k_stats2<<<ROWS/256, 256>>>();
    k_fin2  <<<1, D2>>>(g2, be2);
    k_gemm3 <<<ROWS/64, 256>>>(out);
}

// round 2
// speedup vs baseline: 1.1163x; 1.1163x over previous
#include <cuda_runtime.h>

#define BATCH 4
#define NPTS  16384
#define ROWS  (BATCH*NPTS)     // 65536
#define CIMG  64
#define KIMG  1024
#define D1    128
#define D2    64
#define BN_EPS 1e-5f

// ---------------- scratch (no allocations allowed) ----------------
__device__ __align__(16) float g_y1[(size_t)ROWS*D1];   // 33.5 MB
__device__ __align__(16) float g_y2[(size_t)ROWS*D2];   // 16.8 MB
__device__ float g_gpool[BATCH*CIMG];
__device__ __align__(16) float g_h[BATCH*D1];
__device__ __align__(16) float g_M[BATCH*D2*CIMG];
__device__ __align__(16) float g_dvec[BATCH*CIMG];
__device__ __align__(16) float g_W1t[64*D1];            // [k<64][o<128]  (lidar half of W1)
__device__ __align__(16) float g_W2t[D1*D2];            // [k<128][j<64]
__device__ float g_sum1[D1], g_ss1[D1], g_sum2[D2], g_ss2[D2];
__device__ float g_scale1[D1], g_shift1[D1], g_scale2[D2], g_shift2[D2];

// ---------------- packed fp32x2 helpers (Blackwell FFMA2 path) ----------------
__device__ __forceinline__ unsigned long long pack2(float x, float y) {
    unsigned long long r;
    asm("mov.b64 %0, {%1,%2};" : "=l"(r) : "f"(x), "f"(y));
    return r;
}
__device__ __forceinline__ float2 unpack2(unsigned long long v) {
    float2 f;
    asm("mov.b64 {%0,%1}, %2;" : "=f"(f.x), "=f"(f.y) : "l"(v));
    return f;
}
__device__ __forceinline__ unsigned long long ffma2(unsigned long long a,
                                                    unsigned long long b,
                                                    unsigned long long c) {
    unsigned long long d;
    asm("fma.rn.f32x2 %0, %1, %2, %3;" : "=l"(d) : "l"(a), "l"(b), "l"(c));
    return d;
}

// ---------------- prep: weight transposes + zero stats ----------------
__global__ void k_prep(const float* __restrict__ W1, const float* __restrict__ W2) {
    int i = blockIdx.x * blockDim.x + threadIdx.x;   // 16384 threads
    if (i < 64*D1) {
        int k = i / D1, o = i % D1;
        g_W1t[k*D1 + o] = W1[o*128 + 64 + k];        // lidar channels only
    } else {
        int j2 = i - 64*D1;
        int k = j2 / D2, j = j2 % D2;
        g_W2t[k*D2 + j] = W2[j*D1 + k];
    }
    if (i < D1) { g_sum1[i] = 0.f; g_ss1[i] = 0.f; }
    if (i < D2) { g_sum2[i] = 0.f; g_ss2[i] = 0.f; }
}

// ---------------- pool g, d = img·b3/K, M[b] = (img[b]·W3)/K ----------------
__global__ void k_pool_M(const float* __restrict__ img, const float* __restrict__ W3,
                         const float* __restrict__ b3) {
    __shared__ float srow[4][KIMG];
    __shared__ float red[256], red2[256];
    int b  = blockIdx.x >> 4;
    int cg = blockIdx.x & 15;
    int t  = threadIdx.x;
    int ci = t >> 6, lane = t & 63;
    int c  = cg*4 + ci;
    const float* row = img + (size_t)(b*CIMG + c)*KIMG;

    float s = 0.f, sd = 0.f;
    for (int k = lane; k < KIMG; k += 64) {
        float v = row[k];
        srow[ci][k] = v;
        s += v; sd += v * b3[k];
    }
    red[t] = s; red2[t] = sd;
    __syncthreads();
    for (int off = 32; off >= 1; off >>= 1) {
        if (lane < off) { red[t] += red[t+off]; red2[t] += red2[t+off]; }
        __syncthreads();
    }
    if (lane == 0) {
        g_gpool[b*CIMG + c] = red[t]  * (1.f/KIMG);
        g_dvec [b*CIMG + c] = red2[t] * (1.f/KIMG);
    }
    int j = lane;
    float acc = 0.f;
    #pragma unroll 8
    for (int k = 0; k < KIMG; ++k) acc += srow[ci][k] * W3[k*D2 + j];
    g_M[b*(D2*CIMG) + j*CIMG + c] = acc * (1.f/KIMG);
}

// ---------------- h[b,o] = g[b]·W1[o,:64] + b1[o] ----------------
__global__ void k_h(const float* __restrict__ W1, const float* __restrict__ b1) {
    int t = threadIdx.x;          // 512
    int b = t >> 7, o = t & 127;
    float acc = b1[o];
    #pragma unroll 8
    for (int c = 0; c < 64; ++c) acc += g_gpool[b*CIMG + c] * W1[o*128 + c];
    g_h[b*D1 + o] = acc;
}

// ================ GEMM1: y1 = lidar·W1tᵀ + h  [64x128 tile, K=64] + fused stats ================
__global__ __launch_bounds__(128) void k_gemm1(const float* __restrict__ lidar) {
    __shared__ float As[64*65];     // row-major, pad 65
    __shared__ float Bs[64*D1];     // k-major
    int t  = threadIdx.x;
    int tx = t & 15, ty = t >> 4;   // 16 x 8
    size_t r0 = (size_t)blockIdx.x * 64;
    int bidx = (int)(blockIdx.x >> 8);

    // load A tile (coalesced), scatter to padded rows
    {
        const float4* src = (const float4*)(lidar + r0*64);
        #pragma unroll
        for (int i = 0; i < 8; ++i) {
            int f = t + 128*i;
            int row = f >> 4, c4 = f & 15;
            float4 v = src[f];
            float* d = &As[row*65 + c4*4];
            d[0] = v.x; d[1] = v.y; d[2] = v.z; d[3] = v.w;
        }
    }
    // load B (k-major already)
    #pragma unroll
    for (int i = 0; i < 16; ++i)
        ((float4*)Bs)[t + 128*i] = ((const float4*)g_W1t)[t + 128*i];
    __syncthreads();

    unsigned long long acc[8][4] = {};
    #pragma unroll 4
    for (int k = 0; k < 64; ++k) {
        unsigned long long ap[8];
        #pragma unroll
        for (int i = 0; i < 8; ++i) {
            float a = As[(ty*8+i)*65 + k];
            ap[i] = pack2(a, a);
        }
        float4 b0 = *(const float4*)&Bs[k*D1 + tx*8];
        float4 b1 = *(const float4*)&Bs[k*D1 + tx*8 + 4];
        unsigned long long bp[4] = { pack2(b0.x,b0.y), pack2(b0.z,b0.w),
                                     pack2(b1.x,b1.y), pack2(b1.z,b1.w) };
        #pragma unroll
        for (int i = 0; i < 8; ++i)
            #pragma unroll
            for (int j = 0; j < 4; ++j)
                acc[i][j] = ffma2(ap[i], bp[j], acc[i][j]);
    }

    // epilogue: +h, write y1, per-channel partial stats
    float4 h0 = *(const float4*)&g_h[bidx*D1 + tx*8];
    float4 h1 = *(const float4*)&g_h[bidx*D1 + tx*8 + 4];
    float hs[8] = {h0.x,h0.y,h0.z,h0.w,h1.x,h1.y,h1.z,h1.w};
    float csum[8], csq[8];
    #pragma unroll
    for (int c = 0; c < 8; ++c) { csum[c] = 0.f; csq[c] = 0.f; }
    #pragma unroll
    for (int i = 0; i < 8; ++i) {
        float o[8];
        #pragma unroll
        for (int j = 0; j < 4; ++j) {
            float2 v = unpack2(acc[i][j]);
            o[2*j]   = v.x + hs[2*j];
            o[2*j+1] = v.y + hs[2*j+1];
        }
        #pragma unroll
        for (int c = 0; c < 8; ++c) { csum[c] += o[c]; csq[c] += o[c]*o[c]; }
        float* dst = &g_y1[(r0 + ty*8 + i)*D1 + tx*8];
        *(float4*)dst     = make_float4(o[0],o[1],o[2],o[3]);
        *(float4*)(dst+4) = make_float4(o[4],o[5],o[6],o[7]);
    }
    __syncthreads();
    float* ssum = As;            // reuse (need 2*1024 floats <= 4160)
    float* ssq  = As + 1024;
    #pragma unroll
    for (int c = 0; c < 8; ++c) {
        ssum[ty*128 + tx*8 + c] = csum[c];
        ssq [ty*128 + tx*8 + c] = csq[c];
    }
    __syncthreads();
    if (t < D1) {
        float s = 0.f, q = 0.f;
        #pragma unroll
        for (int y = 0; y < 8; ++y) { s += ssum[y*128 + t]; q += ssq[y*128 + t]; }
        atomicAdd(&g_sum1[t], s);
        atomicAdd(&g_ss1[t],  q);
    }
}

__global__ void k_fin1(const float* __restrict__ g1, const float* __restrict__ be1) {
    int t = threadIdx.x;   // 128
    const float inv = 1.f / (float)ROWS;
    float mu  = g_sum1[t] * inv;
    float var = fmaxf(g_ss1[t] * inv - mu*mu, 0.f);
    float scale = g1[t] * rsqrtf(var + BN_EPS);
    g_scale1[t] = scale;
    g_shift1[t] = be1[t] - mu*scale;
}

// ================ GEMM2: y2 = relu(bn1(y1))·W2tᵀ + b2  [128x64 tile, K=128] + fused stats ================
__global__ __launch_bounds__(128) void k_gemm2(const float* __restrict__ b2) {
    __shared__ float As[128*65];    // 8320 floats
    __shared__ float Bs[64*D2];     // 4096
    __shared__ float sc[D1], sh[D1];
    int t  = threadIdx.x;
    int tx = t & 7, ty = t >> 3;    // 8 x 16
    size_t r0 = (size_t)blockIdx.x * 128;
    if (t < D1) { sc[t] = g_scale1[t]; sh[t] = g_shift1[t]; }
    __syncthreads();

    unsigned long long acc[8][4] = {};
    for (int kh = 0; kh < 2; ++kh) {
        // load A stage: 128 rows x 64 k, bn+relu applied
        #pragma unroll
        for (int i = 0; i < 16; ++i) {
            int f = t + 128*i;
            int row = f >> 4, c4 = f & 15;
            float4 v = *(const float4*)&g_y1[(r0 + row)*D1 + kh*64 + c4*4];
            int ch = kh*64 + c4*4;
            v.x = fmaxf(fmaf(v.x, sc[ch  ], sh[ch  ]), 0.f);
            v.y = fmaxf(fmaf(v.y, sc[ch+1], sh[ch+1]), 0.f);
            v.z = fmaxf(fmaf(v.z, sc[ch+2], sh[ch+2]), 0.f);
            v.w = fmaxf(fmaf(v.w, sc[ch+3], sh[ch+3]), 0.f);
            float* d = &As[row*65 + c4*4];
            d[0] = v.x; d[1] = v.y; d[2] = v.z; d[3] = v.w;
        }
        #pragma unroll
        for (int i = 0; i < 8; ++i)
            ((float4*)Bs)[t + 128*i] = ((const float4*)(g_W2t + kh*64*D2))[t + 128*i];
        __syncthreads();

        #pragma unroll 4
        for (int k = 0; k < 64; ++k) {
            unsigned long long ap[8];
            #pragma unroll
            for (int i = 0; i < 8; ++i) {
                float a = As[(ty*8+i)*65 + k];
                ap[i] = pack2(a, a);
            }
            float4 b0 = *(const float4*)&Bs[k*D2 + tx*8];
            float4 b1 = *(const float4*)&Bs[k*D2 + tx*8 + 4];
            unsigned long long bp[4] = { pack2(b0.x,b0.y), pack2(b0.z,b0.w),
                                         pack2(b1.x,b1.y), pack2(b1.z,b1.w) };
            #pragma unroll
            for (int i = 0; i < 8; ++i)
                #pragma unroll
                for (int j = 0; j < 4; ++j)
                    acc[i][j] = ffma2(ap[i], bp[j], acc[i][j]);
        }
        __syncthreads();
    }

    // epilogue: +b2, write y2, fused stats
    float4 bb0 = *(const float4*)&b2[tx*8];
    float4 bb1 = *(const float4*)&b2[tx*8 + 4];
    float bs[8] = {bb0.x,bb0.y,bb0.z,bb0.w,bb1.x,bb1.y,bb1.z,bb1.w};
    float csum[8], csq[8];
    #pragma unroll
    for (int c = 0; c < 8; ++c) { csum[c] = 0.f; csq[c] = 0.f; }
    #pragma unroll
    for (int i = 0; i < 8; ++i) {
        float o[8];
        #pragma unroll
        for (int j = 0; j < 4; ++j) {
            float2 v = unpack2(acc[i][j]);
            o[2*j]   = v.x + bs[2*j];
            o[2*j+1] = v.y + bs[2*j+1];
        }
        #pragma unroll
        for (int c = 0; c < 8; ++c) { csum[c] += o[c]; csq[c] += o[c]*o[c]; }
        float* dst = &g_y2[(r0 + ty*8 + i)*D2 + tx*8];
        *(float4*)dst     = make_float4(o[0],o[1],o[2],o[3]);
        *(float4*)(dst+4) = make_float4(o[4],o[5],o[6],o[7]);
    }
    __syncthreads();
    float* ssum = As;            // 16*64*2 = 2048 floats <= 8320
    float* ssq  = As + 1024;
    #pragma unroll
    for (int c = 0; c < 8; ++c) {
        ssum[ty*64 + tx*8 + c] = csum[c];
        ssq [ty*64 + tx*8 + c] = csq[c];
    }
    __syncthreads();
    if (t < D2) {
        float s = 0.f, q = 0.f;
        #pragma unroll
        for (int y = 0; y < 16; ++y) { s += ssum[y*64 + t]; q += ssq[y*64 + t]; }
        atomicAdd(&g_sum2[t], s);
        atomicAdd(&g_ss2[t],  q);
    }
}

__global__ void k_fin2(const float* __restrict__ g2, const float* __restrict__ be2) {
    int t = threadIdx.x;   // 64
    const float inv = 1.f / (float)ROWS;
    float mu  = g_sum2[t] * inv;
    float var = fmaxf(g_ss2[t] * inv - mu*mu, 0.f);
    float scale = g2[t] * rsqrtf(var + BN_EPS);
    g_scale2[t] = scale;
    g_shift2[t] = be2[t] - mu*scale;
}

// ================ GEMM3: out = relu(bn2(y2))·M[b] + d[b]  [128x64 tile, K=64] ================
__global__ __launch_bounds__(128) void k_gemm3(float* __restrict__ out) {
    __shared__ float As[128*65];
    __shared__ float Bs[64*64];
    __shared__ float sc[D2], sh[D2];
    int t  = threadIdx.x;
    int tx = t & 7, ty = t >> 3;    // 8 x 16
    size_t r0 = (size_t)blockIdx.x * 128;
    int bidx = (int)(blockIdx.x >> 7);
    if (t < D2) { sc[t] = g_scale2[t]; sh[t] = g_shift2[t]; }
    __syncthreads();

    // load A: 128 rows x 64 k with bn+relu
    #pragma unroll
    for (int i = 0; i < 16; ++i) {
        int f = t + 128*i;
        int row = f >> 4, c4 = f & 15;
        float4 v = *(const float4*)&g_y2[(r0 + row)*D2 + c4*4];
        int ch = c4*4;
        v.x = fmaxf(fmaf(v.x, sc[ch  ], sh[ch  ]), 0.f);
        v.y = fmaxf(fmaf(v.y, sc[ch+1], sh[ch+1]), 0.f);
        v.z = fmaxf(fmaf(v.z, sc[ch+2], sh[ch+2]), 0.f);
        v.w = fmaxf(fmaf(v.w, sc[ch+3], sh[ch+3]), 0.f);
        float* d = &As[row*65 + c4*4];
        d[0] = v.x; d[1] = v.y; d[2] = v.z; d[3] = v.w;
    }
    #pragma unroll
    for (int i = 0; i < 8; ++i)
        ((float4*)Bs)[t + 128*i] = ((const float4*)(g_M + bidx*(D2*CIMG)))[t + 128*i];
    __syncthreads();

    unsigned long long acc[8][4] = {};
    #pragma unroll 4
    for (int k = 0; k < 64; ++k) {
        unsigned long long ap[8];
        #pragma unroll
        for (int i = 0; i < 8; ++i) {
            float a = As[(ty*8+i)*65 + k];
            ap[i] = pack2(a, a);
        }
        float4 b0 = *(const float4*)&Bs[k*64 + tx*8];
        float4 b1 = *(const float4*)&Bs[k*64 + tx*8 + 4];
        unsigned long long bp[4] = { pack2(b0.x,b0.y), pack2(b0.z,b0.w),
                                     pack2(b1.x,b1.y), pack2(b1.z,b1.w) };
        #pragma unroll
        for (int i = 0; i < 8; ++i)
            #pragma unroll
            for (int j = 0; j < 4; ++j)
                acc[i][j] = ffma2(ap[i], bp[j], acc[i][j]);
    }

    float4 d0 = *(const float4*)&g_dvec[bidx*CIMG + tx*8];
    float4 d1 = *(const float4*)&g_dvec[bidx*CIMG + tx*8 + 4];
    float ds[8] = {d0.x,d0.y,d0.z,d0.w,d1.x,d1.y,d1.z,d1.w};
    #pragma unroll
    for (int i = 0; i < 8; ++i) {
        float o[8];
        #pragma unroll
        for (int j = 0; j < 4; ++j) {
            float2 v = unpack2(acc[i][j]);
            o[2*j]   = v.x + ds[2*j];
            o[2*j+1] = v.y + ds[2*j+1];
        }
        float* dst = &out[(r0 + ty*8 + i)*64 + tx*8];
        *(float4*)dst     = make_float4(o[0],o[1],o[2],o[3]);
        *(float4*)(dst+4) = make_float4(o[4],o[5],o[6],o[7]);
    }
}

// ---------------- launch ----------------
extern "C" void kernel_launch(void* const* d_in, const int* in_sizes, int n_in,
                              void* d_out, int out_size) {
    (void)in_sizes; (void)n_in; (void)out_size;
    const float* lidar = (const float*)d_in[0];
    const float* img   = (const float*)d_in[1];
    const float* W1  = (const float*)d_in[2];
    const float* b1  = (const float*)d_in[3];
    const float* g1  = (const float*)d_in[4];
    const float* be1 = (const float*)d_in[5];
    const float* W2  = (const float*)d_in[6];
    const float* b2  = (const float*)d_in[7];
    const float* g2  = (const float*)d_in[8];
    const float* be2 = (const float*)d_in[9];
    const float* W3  = (const float*)d_in[10];
    const float* b3  = (const float*)d_in[11];
    float* out = (float*)d_out;

    k_prep  <<<64, 256>>>(W1, W2);
    k_pool_M<<<64, 256>>>(img, W3, b3);
    k_h     <<<1, 512>>>(W1, b1);
    k_gemm1 <<<ROWS/64, 128>>>(lidar);
    k_fin1  <<<1, D1>>>(g1, be1);
    k_gemm2 <<<ROWS/128, 128>>>(b2);
    k_fin2  <<<1, D2>>>(g2, be2);
    k_gemm3 <<<ROWS/128, 128>>>(out);
}

// round 4
// speedup vs baseline: 1.4164x; 1.2688x over previous
#include <cuda_runtime.h>
#include <cuda_bf16.h>
#include <cstdint>

#define BATCH 4
#define NPTS  16384
#define ROWS  (BATCH*NPTS)     // 65536
#define CIMG  64
#define KIMG  1024
#define D1    128
#define D2    64
#define BN_EPS 1e-5f

// ---------------- global scratch (no allocations allowed) ----------------
__device__ __align__(16) float g_y1[(size_t)ROWS*D1];   // 33.5 MB
__device__ __align__(16) float g_y2[(size_t)ROWS*D2];   // 16.8 MB
__device__ float g_gpool[BATCH*CIMG];
__device__ __align__(16) float g_h[BATCH*D1];
__device__ __align__(16) float g_dvec[BATCH*CIMG];
__device__ float g_sum1[D1], g_ss1[D1], g_sum2[D2], g_ss2[D2];
__device__ float g_scale1[D1], g_shift1[D1], g_scale2[D2], g_shift2[D2];
// bf16 split weights, [n][k] k-contiguous (".col" B operand layout)
__device__ __align__(16) unsigned short g_B1hi[D1*64],  g_B1lo[D1*64];     // W1 lidar half: 128n x 64k
__device__ __align__(16) unsigned short g_B2hi[D2*D1],  g_B2lo[D2*D1];     // W2: 64n x 128k
__device__ __align__(16) unsigned short g_B3hi[BATCH][CIMG*D2], g_B3lo[BATCH][CIMG*D2]; // M_b^T: 64n x 64k

// ---------------- helpers ----------------
__device__ __forceinline__ uint32_t smem_u32(const void* p) {
    uint32_t a;
    asm("{ .reg .u64 t; cvta.to.shared.u64 t, %1; cvt.u32.u64 %0, t; }" : "=r"(a) : "l"(p));
    return a;
}
__device__ __forceinline__ void ldm4(uint32_t a[4], uint32_t addr) {
    asm volatile("ldmatrix.sync.aligned.m8n8.x4.shared.b16 {%0,%1,%2,%3}, [%4];"
        : "=r"(a[0]), "=r"(a[1]), "=r"(a[2]), "=r"(a[3]) : "r"(addr));
}
__device__ __forceinline__ void mma16816(float d[4], const uint32_t a[4], const uint32_t b[2]) {
    asm volatile("mma.sync.aligned.m16n8k16.row.col.f32.bf16.bf16.f32 "
        "{%0,%1,%2,%3}, {%4,%5,%6,%7}, {%8,%9}, {%0,%1,%2,%3};"
        : "+f"(d[0]), "+f"(d[1]), "+f"(d[2]), "+f"(d[3])
        : "r"(a[0]), "r"(a[1]), "r"(a[2]), "r"(a[3]), "r"(b[0]), "r"(b[1]));
}
// split fp32 pair into packed bf16 hi/lo (2 halves per u32)
__device__ __forceinline__ void split2(float a, float b, uint32_t& hi, uint32_t& lo) {
    __nv_bfloat16 ha = __float2bfloat16_rn(a), hb = __float2bfloat16_rn(b);
    float ra = a - __bfloat162float(ha), rb = b - __bfloat162float(hb);
    __nv_bfloat16 la = __float2bfloat16_rn(ra), lb = __float2bfloat16_rn(rb);
    hi = (uint32_t)__bfloat16_as_ushort(ha) | ((uint32_t)__bfloat16_as_ushort(hb) << 16);
    lo = (uint32_t)__bfloat16_as_ushort(la) | ((uint32_t)__bfloat16_as_ushort(lb) << 16);
}
__device__ __forceinline__ void split1(float a, unsigned short& h, unsigned short& l) {
    __nv_bfloat16 bh = __float2bfloat16_rn(a);
    float r = a - __bfloat162float(bh);
    __nv_bfloat16 bl = __float2bfloat16_rn(r);
    h = __bfloat16_as_ushort(bh);
    l = __bfloat16_as_ushort(bl);
}

// ---------------- prep: split weights to bf16 hi/lo + zero stats ----------------
__global__ void k_prep(const float* __restrict__ W1, const float* __restrict__ W2) {
    int i = blockIdx.x * blockDim.x + threadIdx.x;   // 16384 threads
    if (i < D1) { g_sum1[i] = 0.f; g_ss1[i] = 0.f; }
    if (i < D2) { g_sum2[i] = 0.f; g_ss2[i] = 0.f; }
    if (i < 8192) {                 // B1: n 0..127, k 0..63 (lidar channels of W1)
        int n = i >> 6, k = i & 63;
        split1(W1[n*128 + 64 + k], g_B1hi[i], g_B1lo[i]);
    } else {                        // B2: n 0..63, k 0..127
        int idx = i - 8192;
        split1(W2[idx], g_B2hi[idx], g_B2lo[idx]);
    }
}

// ---------------- pool g, d = img·b3/K, B3[b] = (img·W3/K)^T bf16-split ----------------
__global__ void k_pool_M(const float* __restrict__ img, const float* __restrict__ W3,
                         const float* __restrict__ b3) {
    __shared__ float srow[4][KIMG];
    __shared__ float red[256], red2[256];
    int b  = blockIdx.x >> 4;
    int cg = blockIdx.x & 15;
    int t  = threadIdx.x;
    int ci = t >> 6, lane = t & 63;
    int c  = cg*4 + ci;
    const float* row = img + (size_t)(b*CIMG + c)*KIMG;

    float s = 0.f, sd = 0.f;
    for (int k = lane; k < KIMG; k += 64) {
        float v = row[k];
        srow[ci][k] = v;
        s += v; sd += v * b3[k];
    }
    red[t] = s; red2[t] = sd;
    __syncthreads();
    for (int off = 32; off >= 1; off >>= 1) {
        if (lane < off) { red[t] += red[t+off]; red2[t] += red2[t+off]; }
        __syncthreads();
    }
    if (lane == 0) {
        g_gpool[b*CIMG + c] = red[t]  * (1.f/KIMG);
        g_dvec [b*CIMG + c] = red2[t] * (1.f/KIMG);
    }
    int j = lane;
    float acc = 0.f;
    #pragma unroll 8
    for (int k = 0; k < KIMG; ++k) acc += srow[ci][k] * W3[k*D2 + j];
    float m = acc * (1.f/KIMG);      // M[b][j][c]; store as B3 row n=c, col k=j
    split1(m, g_B3hi[b][c*D2 + j], g_B3lo[b][c*D2 + j]);
}

// ---------------- h[b,o] = g[b]·W1[o,:64] + b1[o] ----------------
__global__ void k_h(const float* __restrict__ W1, const float* __restrict__ b1) {
    int t = threadIdx.x;          // 512
    int b = t >> 7, o = t & 127;
    float acc = b1[o];
    #pragma unroll 8
    for (int c = 0; c < 64; ++c) acc += g_gpool[b*CIMG + c] * W1[o*128 + c];
    g_h[b*D1 + o] = acc;
}

__global__ void k_fin1(const float* __restrict__ g1, const float* __restrict__ be1) {
    int t = threadIdx.x;   // 128
    const float inv = 1.f / (float)ROWS;
    float mu  = g_sum1[t] * inv;
    float var = fmaxf(g_ss1[t] * inv - mu*mu, 0.f);
    float scale = g1[t] * rsqrtf(var + BN_EPS);
    g_scale1[t] = scale;
    g_shift1[t] = be1[t] - mu*scale;
}

__global__ void k_fin2(const float* __restrict__ g2, const float* __restrict__ be2) {
    int t = threadIdx.x;   // 64
    const float inv = 1.f / (float)ROWS;
    float mu  = g_sum2[t] * inv;
    float var = fmaxf(g_ss2[t] * inv - mu*mu, 0.f);
    float scale = g2[t] * rsqrtf(var + BN_EPS);
    g_scale2[t] = scale;
    g_shift2[t] = be2[t] - mu*scale;
}

// ================ GEMM1: y1[128,128] = lidar·B1^T + h, fused stats ================
// 256 threads = 8 warps (wm 0..3 x wn 0..1); warp tile 32x64; K=64; pitch 72 halves
#define G1_SMEM 78336
__global__ __launch_bounds__(256, 1) void k_gemm1(const float* __restrict__ lidar) {
    extern __shared__ __align__(16) char sm[];
    uint32_t sb = smem_u32(sm);
    const uint32_t AH = 0, AL = 18432, BH = 36864, BL = 55296,
                   HS = 73728, PS = 74240, PQ = 76288;
    int t = threadIdx.x, lane = t & 31, wid = t >> 5;
    int wm = wid >> 1, wn = wid & 1;
    size_t r0 = (size_t)blockIdx.x * 128;
    int bidx = (int)(blockIdx.x >> 7);

    if (t < 128) *(float*)(sm + HS + t*4) = g_h[bidx*D1 + t];
    // stage A: lidar fp32 -> bf16 hi/lo
    {
        int c4 = t & 15, rb = t >> 4;
        const float4* lp = (const float4*)(lidar + r0*64);
        #pragma unroll
        for (int i = 0; i < 8; ++i) {
            int row = rb + 16*i;
            float4 v = lp[row*16 + c4];
            uint32_t h01, l01, h23, l23;
            split2(v.x, v.y, h01, l01);
            split2(v.z, v.w, h23, l23);
            uint32_t off = (uint32_t)(row*72 + c4*4)*2;
            *(uint2*)(sm + AH + off) = make_uint2(h01, h23);
            *(uint2*)(sm + AL + off) = make_uint2(l01, l23);
        }
    }
    // stage B (global prepacked)
    {
        int c4 = t & 15, nb = t >> 4;
        #pragma unroll
        for (int i = 0; i < 8; ++i) {
            int n = nb + 16*i;
            uint2 vh = ((const uint2*)g_B1hi)[n*16 + c4];
            uint2 vl = ((const uint2*)g_B1lo)[n*16 + c4];
            uint32_t off = (uint32_t)(n*72 + c4*4)*2;
            *(uint2*)(sm + BH + off) = vh;
            *(uint2*)(sm + BL + off) = vl;
        }
    }
    __syncthreads();

    float acc[2][8][4] = {};
    uint32_t aoH = sb + AH + (uint32_t)(((wm*32 + (lane & 15))*72 + (lane >> 4)*8)*2);
    uint32_t aoL = aoH + (AL - AH);
    uint32_t boH = sb + BH + (uint32_t)(((wn*64 + (lane & 15))*72 + (lane >> 4)*8)*2);
    uint32_t boL = boH + (BL - BH);
    #pragma unroll
    for (int ks = 0; ks < 4; ++ks) {
        uint32_t aHf[2][4], aLf[2][4];
        ldm4(aHf[0], aoH + ks*32);
        ldm4(aHf[1], aoH + 16*144 + ks*32);
        ldm4(aLf[0], aoL + ks*32);
        ldm4(aLf[1], aoL + 16*144 + ks*32);
        uint32_t bHf[8][2], bLf[8][2];
        #pragma unroll
        for (int ng = 0; ng < 4; ++ng) {
            uint32_t r[4];
            ldm4(r, boH + ng*16*144 + ks*32);
            bHf[2*ng][0] = r[0]; bHf[2*ng][1] = r[2];
            bHf[2*ng+1][0] = r[1]; bHf[2*ng+1][1] = r[3];
            ldm4(r, boL + ng*16*144 + ks*32);
            bLf[2*ng][0] = r[0]; bLf[2*ng][1] = r[2];
            bLf[2*ng+1][0] = r[1]; bLf[2*ng+1][1] = r[3];
        }
        #pragma unroll
        for (int mt = 0; mt < 2; ++mt)
            #pragma unroll
            for (int nt = 0; nt < 8; ++nt) {
                mma16816(acc[mt][nt], aHf[mt], bHf[nt]);
                mma16816(acc[mt][nt], aHf[mt], bLf[nt]);
                mma16816(acc[mt][nt], aLf[mt], bHf[nt]);
            }
    }

    // epilogue: +h, write y1, fused stats
    float s[8][2], q[8][2];
    #pragma unroll
    for (int nt = 0; nt < 8; ++nt) { s[nt][0]=s[nt][1]=q[nt][0]=q[nt][1]=0.f; }
    int colb = wn*64 + (lane & 3)*2;
    int rb = wm*32 + (lane >> 2);
    #pragma unroll
    for (int nt = 0; nt < 8; ++nt) {
        int col = colb + nt*8;
        float h0 = *(float*)(sm + HS + col*4);
        float h1 = *(float*)(sm + HS + col*4 + 4);
        #pragma unroll
        for (int mt = 0; mt < 2; ++mt) {
            float v0 = acc[mt][nt][0] + h0, v1 = acc[mt][nt][1] + h1;
            float v2 = acc[mt][nt][2] + h0, v3 = acc[mt][nt][3] + h1;
            size_t row = r0 + rb + mt*16;
            *(float2*)&g_y1[row*D1 + col]      = make_float2(v0, v1);
            *(float2*)&g_y1[(row + 8)*D1 + col] = make_float2(v2, v3);
            s[nt][0] += v0 + v2;  s[nt][1] += v1 + v3;
            q[nt][0] += v0*v0 + v2*v2;  q[nt][1] += v1*v1 + v3*v3;
        }
    }
    #pragma unroll
    for (int m = 4; m <= 16; m <<= 1)
        #pragma unroll
        for (int nt = 0; nt < 8; ++nt) {
            s[nt][0] += __shfl_xor_sync(0xffffffffu, s[nt][0], m);
            s[nt][1] += __shfl_xor_sync(0xffffffffu, s[nt][1], m);
            q[nt][0] += __shfl_xor_sync(0xffffffffu, q[nt][0], m);
            q[nt][1] += __shfl_xor_sync(0xffffffffu, q[nt][1], m);
        }
    if (lane < 4) {
        #pragma unroll
        for (int nt = 0; nt < 8; ++nt) {
            int ch = wn*64 + nt*8 + lane*2;
            *(float*)(sm + PS + (wm*128 + ch)*4)     = s[nt][0];
            *(float*)(sm + PS + (wm*128 + ch + 1)*4) = s[nt][1];
            *(float*)(sm + PQ + (wm*128 + ch)*4)     = q[nt][0];
            *(float*)(sm + PQ + (wm*128 + ch + 1)*4) = q[nt][1];
        }
    }
    __syncthreads();
    if (t < 128) {
        float ss = 0.f, qq = 0.f;
        #pragma unroll
        for (int w = 0; w < 4; ++w) {
            ss += *(float*)(sm + PS + (w*128 + t)*4);
            qq += *(float*)(sm + PQ + (w*128 + t)*4);
        }
        atomicAdd(&g_sum1[t], ss);
        atomicAdd(&g_ss1[t],  qq);
    }
}

// ================ GEMM2: y2[128,64] = relu(bn1(y1))·B2^T + b2, fused stats ================
// 128 threads = 4 warps (wm 0..3); warp tile 32x64; K=128; pitch 136 halves
#define G2_SMEM 107776
__global__ __launch_bounds__(128, 1) void k_gemm2(const float* __restrict__ b2) {
    extern __shared__ __align__(16) char sm[];
    uint32_t sb = smem_u32(sm);
    const uint32_t AH = 0, AL = 34816, BH = 69632, BL = 87040,
                   SC = 104448, SH = 104960, BB = 105472, PS = 105728, PQ = 106752;
    int t = threadIdx.x, lane = t & 31, wm = t >> 5;
    size_t r0 = (size_t)blockIdx.x * 128;

    if (t < 128) {
        *(float*)(sm + SC + t*4) = g_scale1[t];
        *(float*)(sm + SH + t*4) = g_shift1[t];
    }
    if (t < 64) *(float*)(sm + BB + t*4) = b2[t];
    __syncthreads();

    // stage A: bn1 + relu + split
    {
        int c4 = t & 31, rb = t >> 5;
        const float4* yp = (const float4*)(g_y1 + r0*D1);
        float s0 = *(float*)(sm + SC + (c4*4  )*4), h0 = *(float*)(sm + SH + (c4*4  )*4);
        float s1 = *(float*)(sm + SC + (c4*4+1)*4), h1 = *(float*)(sm + SH + (c4*4+1)*4);
        float s2 = *(float*)(sm + SC + (c4*4+2)*4), h2 = *(float*)(sm + SH + (c4*4+2)*4);
        float s3 = *(float*)(sm + SC + (c4*4+3)*4), h3 = *(float*)(sm + SH + (c4*4+3)*4);
        #pragma unroll
        for (int i = 0; i < 32; ++i) {
            int row = rb + 4*i;
            float4 v = yp[row*32 + c4];
            v.x = fmaxf(fmaf(v.x, s0, h0), 0.f);
            v.y = fmaxf(fmaf(v.y, s1, h1), 0.f);
            v.z = fmaxf(fmaf(v.z, s2, h2), 0.f);
            v.w = fmaxf(fmaf(v.w, s3, h3), 0.f);
            uint32_t h01, l01, h23, l23;
            split2(v.x, v.y, h01, l01);
            split2(v.z, v.w, h23, l23);
            uint32_t off = (uint32_t)(row*136 + c4*4)*2;
            *(uint2*)(sm + AH + off) = make_uint2(h01, h23);
            *(uint2*)(sm + AL + off) = make_uint2(l01, l23);
        }
    }
    // stage B
    {
        int c4 = t & 31, nb = t >> 5;
        #pragma unroll
        for (int i = 0; i < 16; ++i) {
            int n = nb + 4*i;
            uint2 vh = ((const uint2*)g_B2hi)[n*32 + c4];
            uint2 vl = ((const uint2*)g_B2lo)[n*32 + c4];
            uint32_t off = (uint32_t)(n*136 + c4*4)*2;
            *(uint2*)(sm + BH + off) = vh;
            *(uint2*)(sm + BL + off) = vl;
        }
    }
    __syncthreads();

    float acc[2][8][4] = {};
    uint32_t aoH = sb + AH + (uint32_t)(((wm*32 + (lane & 15))*136 + (lane >> 4)*8)*2);
    uint32_t aoL = aoH + (AL - AH);
    uint32_t boH = sb + BH + (uint32_t)((((lane & 15))*136 + (lane >> 4)*8)*2);
    uint32_t boL = boH + (BL - BH);
    #pragma unroll
    for (int ks = 0; ks < 8; ++ks) {
        uint32_t aHf[2][4], aLf[2][4];
        ldm4(aHf[0], aoH + ks*32);
        ldm4(aHf[1], aoH + 16*272 + ks*32);
        ldm4(aLf[0], aoL + ks*32);
        ldm4(aLf[1], aoL + 16*272 + ks*32);
        uint32_t bHf[8][2], bLf[8][2];
        #pragma unroll
        for (int ng = 0; ng < 4; ++ng) {
            uint32_t r[4];
            ldm4(r, boH + ng*16*272 + ks*32);
            bHf[2*ng][0] = r[0]; bHf[2*ng][1] = r[2];
            bHf[2*ng+1][0] = r[1]; bHf[2*ng+1][1] = r[3];
            ldm4(r, boL + ng*16*272 + ks*32);
            bLf[2*ng][0] = r[0]; bLf[2*ng][1] = r[2];
            bLf[2*ng+1][0] = r[1]; bLf[2*ng+1][1] = r[3];
        }
        #pragma unroll
        for (int mt = 0; mt < 2; ++mt)
            #pragma unroll
            for (int nt = 0; nt < 8; ++nt) {
                mma16816(acc[mt][nt], aHf[mt], bHf[nt]);
                mma16816(acc[mt][nt], aHf[mt], bLf[nt]);
                mma16816(acc[mt][nt], aLf[mt], bHf[nt]);
            }
    }

    float s[8][2], q[8][2];
    #pragma unroll
    for (int nt = 0; nt < 8; ++nt) { s[nt][0]=s[nt][1]=q[nt][0]=q[nt][1]=0.f; }
    int colb = (lane & 3)*2;
    int rb = wm*32 + (lane >> 2);
    #pragma unroll
    for (int nt = 0; nt < 8; ++nt) {
        int col = colb + nt*8;
        float h0 = *(float*)(sm + BB + col*4);
        float h1 = *(float*)(sm + BB + col*4 + 4);
        #pragma unroll
        for (int mt = 0; mt < 2; ++mt) {
            float v0 = acc[mt][nt][0] + h0, v1 = acc[mt][nt][1] + h1;
            float v2 = acc[mt][nt][2] + h0, v3 = acc[mt][nt][3] + h1;
            size_t row = r0 + rb + mt*16;
            *(float2*)&g_y2[row*D2 + col]       = make_float2(v0, v1);
            *(float2*)&g_y2[(row + 8)*D2 + col] = make_float2(v2, v3);
            s[nt][0] += v0 + v2;  s[nt][1] += v1 + v3;
            q[nt][0] += v0*v0 + v2*v2;  q[nt][1] += v1*v1 + v3*v3;
        }
    }
    #pragma unroll
    for (int m = 4; m <= 16; m <<= 1)
        #pragma unroll
        for (int nt = 0; nt < 8; ++nt) {
            s[nt][0] += __shfl_xor_sync(0xffffffffu, s[nt][0], m);
            s[nt][1] += __shfl_xor_sync(0xffffffffu, s[nt][1], m);
            q[nt][0] += __shfl_xor_sync(0xffffffffu, q[nt][0], m);
            q[nt][1] += __shfl_xor_sync(0xffffffffu, q[nt][1], m);
        }
    if (lane < 4) {
        #pragma unroll
        for (int nt = 0; nt < 8; ++nt) {
            int ch = nt*8 + lane*2;
            *(float*)(sm + PS + (wm*64 + ch)*4)     = s[nt][0];
            *(float*)(sm + PS + (wm*64 + ch + 1)*4) = s[nt][1];
            *(float*)(sm + PQ + (wm*64 + ch)*4)     = q[nt][0];
            *(float*)(sm + PQ + (wm*64 + ch + 1)*4) = q[nt][1];
        }
    }
    __syncthreads();
    if (t < 64) {
        float ss = 0.f, qq = 0.f;
        #pragma unroll
        for (int w = 0; w < 4; ++w) {
            ss += *(float*)(sm + PS + (w*64 + t)*4);
            qq += *(float*)(sm + PQ + (w*64 + t)*4);
        }
        atomicAdd(&g_sum2[t], ss);
        atomicAdd(&g_ss2[t],  qq);
    }
}

// ================ GEMM3: out[128,64] = relu(bn2(y2))·B3[b]^T + d[b] ================
// 128 threads = 4 warps; warp tile 32x64; K=64; pitch 72 halves
#define G3_SMEM 56064
__global__ __launch_bounds__(128, 1) void k_gemm3(float* __restrict__ out) {
    extern __shared__ __align__(16) char sm[];
    uint32_t sb = smem_u32(sm);
    const uint32_t AH = 0, AL = 18432, BH = 36864, BL = 46080,
                   SC = 55296, SH = 55552, DV = 55808;
    int t = threadIdx.x, lane = t & 31, wm = t >> 5;
    size_t r0 = (size_t)blockIdx.x * 128;
    int bidx = (int)(blockIdx.x >> 7);

    if (t < 64) {
        *(float*)(sm + SC + t*4) = g_scale2[t];
        *(float*)(sm + SH + t*4) = g_shift2[t];
        *(float*)(sm + DV + t*4) = g_dvec[bidx*CIMG + t];
    }
    __syncthreads();

    // stage A: bn2 + relu + split
    {
        int c4 = t & 15, rb = t >> 4;
        const float4* yp = (const float4*)(g_y2 + r0*D2);
        float s0 = *(float*)(sm + SC + (c4*4  )*4), h0 = *(float*)(sm + SH + (c4*4  )*4);
        float s1 = *(float*)(sm + SC + (c4*4+1)*4), h1 = *(float*)(sm + SH + (c4*4+1)*4);
        float s2 = *(float*)(sm + SC + (c4*4+2)*4), h2 = *(float*)(sm + SH + (c4*4+2)*4);
        float s3 = *(float*)(sm + SC + (c4*4+3)*4), h3 = *(float*)(sm + SH + (c4*4+3)*4);
        #pragma unroll
        for (int i = 0; i < 16; ++i) {
            int row = rb + 8*i;
            float4 v = yp[row*16 + c4];
            v.x = fmaxf(fmaf(v.x, s0, h0), 0.f);
            v.y = fmaxf(fmaf(v.y, s1, h1), 0.f);
            v.z = fmaxf(fmaf(v.z, s2, h2), 0.f);
            v.w = fmaxf(fmaf(v.w, s3, h3), 0.f);
            uint32_t h01, l01, h23, l23;
            split2(v.x, v.y, h01, l01);
            split2(v.z, v.w, h23, l23);
            uint32_t off = (uint32_t)(row*72 + c4*4)*2;
            *(uint2*)(sm + AH + off) = make_uint2(h01, h23);
            *(uint2*)(sm + AL + off) = make_uint2(l01, l23);
        }
    }
    // stage B (per-batch)
    {
        int c4 = t & 15, nb = t >> 4;
        #pragma unroll
        for (int i = 0; i < 8; ++i) {
            int n = nb + 8*i;
            uint2 vh = ((const uint2*)(g_B3hi[bidx]))[n*16 + c4];
            uint2 vl = ((const uint2*)(g_B3lo[bidx]))[n*16 + c4];
            uint32_t off = (uint32_t)(n*72 + c4*4)*2;
            *(uint2*)(sm + BH + off) = vh;
            *(uint2*)(sm + BL + off) = vl;
        }
    }
    __syncthreads();

    float acc[2][8][4] = {};
    uint32_t aoH = sb + AH + (uint32_t)(((wm*32 + (lane & 15))*72 + (lane >> 4)*8)*2);
    uint32_t aoL = aoH + (AL - AH);
    uint32_t boH = sb + BH + (uint32_t)((((lane & 15))*72 + (lane >> 4)*8)*2);
    uint32_t boL = boH + (BL - BH);
    #pragma unroll
    for (int ks = 0; ks < 4; ++ks) {
        uint32_t aHf[2][4], aLf[2][4];
        ldm4(aHf[0], aoH + ks*32);
        ldm4(aHf[1], aoH + 16*144 + ks*32);
        ldm4(aLf[0], aoL + ks*32);
        ldm4(aLf[1], aoL + 16*144 + ks*32);
        uint32_t bHf[8][2], bLf[8][2];
        #pragma unroll
        for (int ng = 0; ng < 4; ++ng) {
            uint32_t r[4];
            ldm4(r, boH + ng*16*144 + ks*32);
            bHf[2*ng][0] = r[0]; bHf[2*ng][1] = r[2];
            bHf[2*ng+1][0] = r[1]; bHf[2*ng+1][1] = r[3];
            ldm4(r, boL + ng*16*144 + ks*32);
            bLf[2*ng][0] = r[0]; bLf[2*ng][1] = r[2];
            bLf[2*ng+1][0] = r[1]; bLf[2*ng+1][1] = r[3];
        }
        #pragma unroll
        for (int mt = 0; mt < 2; ++mt)
            #pragma unroll
            for (int nt = 0; nt < 8; ++nt) {
                mma16816(acc[mt][nt], aHf[mt], bHf[nt]);
                mma16816(acc[mt][nt], aHf[mt], bLf[nt]);
                mma16816(acc[mt][nt], aLf[mt], bHf[nt]);
            }
    }

    int colb = (lane & 3)*2;
    int rb = wm*32 + (lane >> 2);
    #pragma unroll
    for (int nt = 0; nt < 8; ++nt) {
        int col = colb + nt*8;
        float d0 = *(float*)(sm + DV + col*4);
        float d1 = *(float*)(sm + DV + col*4 + 4);
        #pragma unroll
        for (int mt = 0; mt < 2; ++mt) {
            size_t row = r0 + rb + mt*16;
            *(float2*)&out[row*64 + col] =
                make_float2(acc[mt][nt][0] + d0, acc[mt][nt][1] + d1);
            *(float2*)&out[(row + 8)*64 + col] =
                make_float2(acc[mt][nt][2] + d0, acc[mt][nt][3] + d1);
        }
    }
}

// ---------------- launch ----------------
extern "C" void kernel_launch(void* const* d_in, const int* in_sizes, int n_in,
                              void* d_out, int out_size) {
    (void)in_sizes; (void)n_in; (void)out_size;
    const float* lidar = (const float*)d_in[0];
    const float* img   = (const float*)d_in[1];
    const float* W1  = (const float*)d_in[2];
    const float* b1  = (const float*)d_in[3];
    const float* g1  = (const float*)d_in[4];
    const float* be1 = (const float*)d_in[5];
    const float* W2  = (const float*)d_in[6];
    const float* b2  = (const float*)d_in[7];
    const float* g2  = (const float*)d_in[8];
    const float* be2 = (const float*)d_in[9];
    const float* W3  = (const float*)d_in[10];
    const float* b3  = (const float*)d_in[11];
    float* out = (float*)d_out;

    cudaFuncSetAttribute(k_gemm1, cudaFuncAttributeMaxDynamicSharedMemorySize, G1_SMEM);
    cudaFuncSetAttribute(k_gemm2, cudaFuncAttributeMaxDynamicSharedMemorySize, G2_SMEM);
    cudaFuncSetAttribute(k_gemm3, cudaFuncAttributeMaxDynamicSharedMemorySize, G3_SMEM);

    k_prep  <<<64, 256>>>(W1, W2);
    k_pool_M<<<64, 256>>>(img, W3, b3);
    k_h     <<<1, 512>>>(W1, b1);
    k_gemm1 <<<ROWS/128, 256, G1_SMEM>>>(lidar);
    k_fin1  <<<1, D1>>>(g1, be1);
    k_gemm2 <<<ROWS/128, 128, G2_SMEM>>>(b2);
    k_fin2  <<<1, D2>>>(g2, be2);
    k_gemm3 <<<ROWS/128, 128, G3_SMEM>>>(out);
}